// round 2
// baseline (speedup 1.0000x reference)
#include <cuda_runtime.h>
#include <math.h>

// Scratch: scores matrix (B*N floats, B=256, N=4096 -> 4 MB) + accumulator.
__device__ float g_scores[256 * 4096];
__device__ double g_acc;

// ---------------------------------------------------------------------------
// Kernel 0: zero the accumulator
// ---------------------------------------------------------------------------
__global__ void init_kernel() {
    g_acc = 0.0;
}

// ---------------------------------------------------------------------------
// Kernel 1: scores[b,n] = dot(X[b,n,:], W) + b0.  D=64.
// 16 lanes per score, float4 loads (1 LDG.128 per lane), xor-shuffle reduce.
// ---------------------------------------------------------------------------
__global__ void scores_kernel(const float* __restrict__ X,
                              const float* __restrict__ W,
                              const float* __restrict__ bias,
                              float* __restrict__ scores,
                              int total_scores) {
    int g = blockIdx.x * blockDim.x + threadIdx.x;
    int sidx = g >> 4;          // score index
    int l    = g & 15;          // lane within 16-group
    if (sidx >= total_scores) return;

    const float4 xv = reinterpret_cast<const float4*>(X + (size_t)sidx * 64)[l];
    const float4 wv = reinterpret_cast<const float4*>(W)[l];

    float p = xv.x * wv.x + xv.y * wv.y + xv.z * wv.z + xv.w * wv.w;
    p += __shfl_xor_sync(0xFFFFFFFFu, p, 8);
    p += __shfl_xor_sync(0xFFFFFFFFu, p, 4);
    p += __shfl_xor_sync(0xFFFFFFFFu, p, 2);
    p += __shfl_xor_sync(0xFFFFFFFFu, p, 1);

    if (l == 0) scores[sidx] = p + bias[0];
}

// ---------------------------------------------------------------------------
// Kernel 2: per batch row — gather by ranking, reverse (suffix) logsumexp
// scan, accumulate sum_i (rs_i - denom_i).  One block per row.
// N = 4096, 128 threads, 32 elements/thread.
// logsumexp state: (m, s) meaning log(sum exp) = m + log(s).
// ---------------------------------------------------------------------------
#define NN 4096
#define T2 128
#define CHUNK (NN / T2)   // 32

__global__ __launch_bounds__(T2) void nll_kernel(const float* __restrict__ scores,
                                                 const int* __restrict__ rankings) {
    __shared__ float s_sc[NN];   // scores row
    __shared__ float s_rs[NN];   // gathered ranking scores
    __shared__ float s_m[T2];
    __shared__ float s_sv[T2];
    __shared__ float s_red[T2 / 32];

    const int b = blockIdx.x;
    const float* srow = scores   + (size_t)b * NN;
    const int*   rrow = rankings + (size_t)b * NN;

    // Stage scores row into smem (coalesced).
    for (int i = threadIdx.x; i < NN; i += T2) s_sc[i] = srow[i];
    __syncthreads();

    // Gather by ranking (coalesced ranking reads; smem random gather).
    for (int i = threadIdx.x; i < NN; i += T2) {
        int idx = rrow[i] & (NN - 1);   // safety clamp (indices are in [0, N))
        s_rs[i] = s_sc[idx];
    }
    __syncthreads();

    const int c    = threadIdx.x;     // chunk id
    const int base = c * CHUNK;

    // Pass 1: local suffix aggregate of this chunk (high -> low).
    float m = -INFINITY, sv = 0.0f;
    #pragma unroll
    for (int j = CHUNK - 1; j >= 0; j--) {
        float x = s_rs[base + j];
        if (x > m) { sv = sv * __expf(m - x) + 1.0f; m = x; }
        else       { sv += __expf(x - m); }
    }
    s_m[c] = m; s_sv[c] = sv;
    __syncthreads();

    // Inclusive suffix scan over the 128 chunk aggregates (Hillis-Steele).
    #pragma unroll
    for (int d = 1; d < T2; d <<= 1) {
        float m2 = s_m[c], sv2 = s_sv[c];
        if (c + d < T2) {
            float mo = s_m[c + d], so = s_sv[c + d];
            if (mo > m2) { sv2 = sv2 * __expf(m2 - mo) + so; m2 = mo; }
            else         { sv2 += so * __expf(mo - m2); }
        }
        __syncthreads();
        s_m[c] = m2; s_sv[c] = sv2;
        __syncthreads();
    }

    // Exclusive suffix carry for this chunk.
    const float Mc = (c < T2 - 1) ? s_m[c + 1]  : -INFINITY;
    const float Sc = (c < T2 - 1) ? s_sv[c + 1] : 0.0f;

    // Pass 2: replay chunk, emit denom per element, accumulate (x - denom).
    m = -INFINITY; sv = 0.0f;
    float acc = 0.0f;
    #pragma unroll
    for (int j = CHUNK - 1; j >= 0; j--) {
        float x = s_rs[base + j];
        if (x > m) { sv = sv * __expf(m - x) + 1.0f; m = x; }
        else       { sv += __expf(x - m); }
        float denom;
        if (m >= Mc) denom = m  + __logf(sv + Sc * __expf(Mc - m));  // Sc==0: 0*exp(-inf)=0, fine
        else         denom = Mc + __logf(Sc + sv * __expf(m - Mc));
        acc += x - denom;
    }

    // Block reduce acc -> atomic add (double) to global accumulator.
    #pragma unroll
    for (int o = 16; o; o >>= 1) acc += __shfl_xor_sync(0xFFFFFFFFu, acc, o);
    if ((threadIdx.x & 31) == 0) s_red[threadIdx.x >> 5] = acc;
    __syncthreads();
    if (threadIdx.x == 0) {
        double t = 0.0;
        #pragma unroll
        for (int w = 0; w < T2 / 32; w++) t += (double)s_red[w];
        atomicAdd(&g_acc, t);
    }
}

// ---------------------------------------------------------------------------
// Kernel 3: finalize  nll = -acc / B
// ---------------------------------------------------------------------------
__global__ void finalize_kernel(float* __restrict__ out, int B) {
    out[0] = (float)(-g_acc / (double)B);
}

extern "C" void kernel_launch(void* const* d_in, const int* in_sizes, int n_in,
                              void* d_out, int out_size) {
    const float* X        = (const float*)d_in[0];
    const float* W        = (const float*)d_in[1];
    const float* bias     = (const float*)d_in[2];
    const int*   rankings = (const int*)d_in[3];
    float* out = (float*)d_out;

    const int BN = in_sizes[3];        // B * N elements
    const int B  = BN / NN;            // N fixed at 4096 for this problem

    init_kernel<<<1, 1>>>();

    // Kernel 1: 16 threads per score.
    {
        long long threads_needed = (long long)BN * 16;
        int tpb = 256;
        int blocks = (int)((threads_needed + tpb - 1) / tpb);
        scores_kernel<<<blocks, tpb>>>(X, W, bias, g_scores, BN);
    }

    // Kernel 2: one block per batch row.
    nll_kernel<<<B, T2>>>(g_scores, rankings);

    finalize_kernel<<<1, 1>>>(out, B);
}

// round 3
// speedup vs baseline: 3.8560x; 3.8560x over previous
#include <cuda_runtime.h>
#include <math.h>

#define NN    4096
#define DD    64
#define T     1024
#define CHUNK (NN / T)        // 4 elements per thread
#define FULL  0xFFFFFFFFu

// logsumexp pair combine: (m1,s1) <- (m1,s1) ⊕ (m2,s2), log(sum) = m + log(s)
__device__ __forceinline__ void lse_combine(float& m1, float& s1, float m2, float s2) {
    if (m2 > m1) { s1 = s1 * __expf(m1 - m2) + s2; m1 = m2; }
    else         { s1 = s1 + s2 * __expf(m2 - m1); }
}

// accumulate one sample x into running (m,sv)
__device__ __forceinline__ void lse_push(float& m, float& sv, float x) {
    if (x > m) { sv = sv * __expf(m - x) + 1.0f; m = x; }
    else       { sv += __expf(x - m); }
}

__global__ void zero_out_kernel(float* out) { out[0] = 0.0f; }

__global__ __launch_bounds__(T) void fused_kernel(const float* __restrict__ X,
                                                  const float* __restrict__ W,
                                                  const float* __restrict__ bias,
                                                  const int* __restrict__ rankings,
                                                  float* __restrict__ out) {
    __shared__ float s_sc[NN];     // scores for this batch row
    __shared__ float s_wm[32];     // per-warp suffix aggregates (max)
    __shared__ float s_ws[32];     // per-warp suffix aggregates (scaled sum)
    __shared__ float s_red[32];    // final reduction

    const int b    = blockIdx.x;
    const int tid  = threadIdx.x;
    const int grp  = tid >> 4;      // 0..63 : which score in the 64-wide stripe
    const int gl   = tid & 15;      // lane within 16-lane dot group
    const int lane = tid & 31;
    const int wrp  = tid >> 5;      // 0..31

    // -------- Phase 1: scores[b, :] = X[b] @ W + b0 ------------------------
    const float4 wv = reinterpret_cast<const float4*>(W)[gl];
    const float  b0 = bias[0];
    const float* Xb = X + (size_t)b * NN * DD;

    #pragma unroll 4
    for (int k = 0; k < NN / 64; k++) {           // 64 iterations
        const int s = k * 64 + grp;
        const float4 xv = reinterpret_cast<const float4*>(Xb + (size_t)s * DD)[gl];
        float p = xv.x * wv.x + xv.y * wv.y + xv.z * wv.z + xv.w * wv.w;
        p += __shfl_xor_sync(FULL, p, 8);
        p += __shfl_xor_sync(FULL, p, 4);
        p += __shfl_xor_sync(FULL, p, 2);
        p += __shfl_xor_sync(FULL, p, 1);
        if (gl == 0) s_sc[s] = p + b0;
    }
    __syncthreads();

    // -------- Phase 2: gather 4 elements by ranking ------------------------
    const int4 r = reinterpret_cast<const int4*>(rankings + (size_t)b * NN)[tid];
    const float x0 = s_sc[r.x & (NN - 1)];
    const float x1 = s_sc[r.y & (NN - 1)];
    const float x2 = s_sc[r.z & (NN - 1)];
    const float x3 = s_sc[r.w & (NN - 1)];

    // -------- Phase 3: local suffix aggregate (x3 -> x0) --------------------
    float m = x3, sv = 1.0f;
    lse_push(m, sv, x2);
    lse_push(m, sv, x1);
    lse_push(m, sv, x0);

    // -------- Phase 4: warp inclusive suffix scan (lane l = lanes l..31) ----
    float mm = m, ss = sv;
    #pragma unroll
    for (int d = 1; d < 32; d <<= 1) {
        const float mo = __shfl_down_sync(FULL, mm, d);
        const float so = __shfl_down_sync(FULL, ss, d);
        if (lane + d < 32) lse_combine(mm, ss, mo, so);
    }
    if (lane == 0) { s_wm[wrp] = mm; s_ws[wrp] = ss; }  // whole-warp aggregate
    __syncthreads();

    // warp 0: inclusive suffix scan over the 32 warp aggregates
    if (wrp == 0) {
        float am = s_wm[lane], as = s_ws[lane];
        #pragma unroll
        for (int d = 1; d < 32; d <<= 1) {
            const float mo = __shfl_down_sync(FULL, am, d);
            const float so = __shfl_down_sync(FULL, as, d);
            if (lane + d < 32) lse_combine(am, as, mo, so);
        }
        s_wm[lane] = am; s_ws[lane] = as;   // inclusive over warps lane..31
    }
    __syncthreads();

    // -------- Phase 5: exclusive suffix carry for this thread ---------------
    // within-warp exclusive = inclusive at lane+1
    const float em_raw = __shfl_down_sync(FULL, mm, 1);
    const float es_raw = __shfl_down_sync(FULL, ss, 1);
    const float em = (lane < 31) ? em_raw : -INFINITY;
    const float es = (lane < 31) ? es_raw : 0.0f;
    // warps above
    const float cm = (wrp < 31) ? s_wm[wrp + 1] : -INFINITY;
    const float cs = (wrp < 31) ? s_ws[wrp + 1] : 0.0f;

    float Mc, Sc;
    if (cm > em)                 { Sc = es * __expf(em - cm) + cs; Mc = cm; }
    else if (em > -INFINITY)     { Sc = es + cs * __expf(cm - em); Mc = em; }
    else                         { Mc = -INFINITY; Sc = 0.0f; }

    // -------- Phase 6: replay chunk, emit denom per element -----------------
    float rm = -INFINITY, rs = 0.0f, acc = 0.0f;
    const float xs[4] = {x3, x2, x1, x0};
    #pragma unroll
    for (int j = 0; j < 4; j++) {
        const float x = xs[j];
        lse_push(rm, rs, x);
        float denom;
        if (rm >= Mc) denom = rm + __logf(rs + Sc * __expf(Mc - rm)); // Sc=0 path: 0*exp(-inf)=0
        else          denom = Mc + __logf(Sc + rs * __expf(rm - Mc));
        acc += x - denom;
    }

    // -------- Phase 7: block reduce, atomic add -----------------------------
    #pragma unroll
    for (int o = 16; o; o >>= 1) acc += __shfl_xor_sync(FULL, acc, o);
    if (lane == 0) s_red[wrp] = acc;
    __syncthreads();
    if (tid == 0) {
        float t = 0.0f;
        #pragma unroll
        for (int w = 0; w < 32; w++) t += s_red[w];
        atomicAdd(out, -t / (float)gridDim.x);
    }
}

extern "C" void kernel_launch(void* const* d_in, const int* in_sizes, int n_in,
                              void* d_out, int out_size) {
    const float* X        = (const float*)d_in[0];
    const float* W        = (const float*)d_in[1];
    const float* bias     = (const float*)d_in[2];
    const int*   rankings = (const int*)d_in[3];
    float* out = (float*)d_out;

    const int BN = in_sizes[3];   // B * N
    const int B  = BN / NN;       // N fixed at 4096

    zero_out_kernel<<<1, 1>>>(out);
    fused_kernel<<<B, T>>>(X, W, bias, rankings, out);
}